// round 1
// baseline (speedup 1.0000x reference)
#include <cuda_runtime.h>
#include <cuda_bf16.h>
#include <math.h>

// Problem dims (fixed by the reference)
#define BB    2
#define NN    2048
#define CC    1024
#define HH    16
#define DD    64
#define HID   4096
#define MROWS (BB * NN)          // 4096

// ---------------------------------------------------------------------------
// Scratch (device globals; no allocation allowed)
// ---------------------------------------------------------------------------
__device__ __align__(16) float g_h  [MROWS * CC];       // LN1 out
__device__ __align__(16) float g_qkv[MROWS * 3 * CC];   // qkv
__device__ __align__(16) float g_o  [MROWS * CC];       // attention out
__device__ __align__(16) float g_x2 [MROWS * CC];       // x + proj
__device__ __align__(16) float g_h2 [MROWS * CC];       // LN2 out
__device__ __align__(16) float g_hh [MROWS * HID];      // gelu(fc1)

// ---------------------------------------------------------------------------
// LayerNorm: one block per row of 1024
// ---------------------------------------------------------------------------
__global__ __launch_bounds__(256) void ln_kernel(
    const float* __restrict__ x, const float* __restrict__ g,
    const float* __restrict__ b, float* __restrict__ y)
{
    __shared__ float red[16];
    const int row = blockIdx.x;
    const int tid = threadIdx.x;
    const float* xr = x + (size_t)row * CC;

    float4 xv = *(const float4*)&xr[tid * 4];
    float s  = xv.x + xv.y + xv.z + xv.w;
    float s2 = xv.x*xv.x + xv.y*xv.y + xv.z*xv.z + xv.w*xv.w;
    #pragma unroll
    for (int o = 16; o > 0; o >>= 1) {
        s  += __shfl_xor_sync(0xffffffffu, s,  o);
        s2 += __shfl_xor_sync(0xffffffffu, s2, o);
    }
    const int warp = tid >> 5;
    if ((tid & 31) == 0) { red[warp] = s; red[warp + 8] = s2; }
    __syncthreads();
    if (tid < 32) {
        float a  = (tid < 8) ? red[tid]     : 0.f;
        float a2 = (tid < 8) ? red[tid + 8] : 0.f;
        #pragma unroll
        for (int o = 4; o > 0; o >>= 1) {
            a  += __shfl_xor_sync(0xffffffffu, a,  o);
            a2 += __shfl_xor_sync(0xffffffffu, a2, o);
        }
        if (tid == 0) { red[0] = a; red[1] = a2; }
    }
    __syncthreads();

    const float mean = red[0] * (1.f / CC);
    const float var  = red[1] * (1.f / CC) - mean * mean;
    const float inv  = rsqrtf(var + 1e-5f);

    float4 gv = *(const float4*)&g[tid * 4];
    float4 bv = *(const float4*)&b[tid * 4];
    float4 yv;
    yv.x = (xv.x - mean) * inv * gv.x + bv.x;
    yv.y = (xv.y - mean) * inv * gv.y + bv.y;
    yv.z = (xv.z - mean) * inv * gv.z + bv.z;
    yv.w = (xv.w - mean) * inv * gv.w + bv.w;
    *(float4*)&y[(size_t)row * CC + tid * 4] = yv;
}

// ---------------------------------------------------------------------------
// Generic fp32 GEMM: C = epilogue(A[M,K] @ B[K,N])
//   epilogue: +bias (if bias), exact-erf GELU (if do_gelu), +resid (if resid)
// 128x128 tile, BK=16, 256 threads, 8x8 per-thread
// ---------------------------------------------------------------------------
#define BM 128
#define BN 128
#define BK 16

__global__ __launch_bounds__(256) void gemm_kernel(
    const float* __restrict__ A, const float* __restrict__ B,
    const float* __restrict__ bias, const float* __restrict__ resid,
    float* __restrict__ C, int M, int N, int K, int do_gelu)
{
    __shared__ float As[BK][BM];
    __shared__ float Bs[BK][BN];

    const int tid  = threadIdx.x;
    const int row0 = blockIdx.y * BM;
    const int col0 = blockIdx.x * BN;
    const int tm0  = (tid / 16) * 8;
    const int tn0  = (tid % 16) * 8;

    float acc[8][8];
    #pragma unroll
    for (int i = 0; i < 8; i++)
        #pragma unroll
        for (int j = 0; j < 8; j++) acc[i][j] = 0.f;

    for (int k0 = 0; k0 < K; k0 += BK) {
        // A tile 128x16 -> As[k][m] (transposed)
        #pragma unroll
        for (int it = 0; it < 2; it++) {
            int idx = tid + it * 256;
            int r   = idx >> 2;
            int c4  = (idx & 3) * 4;
            float4 v = *(const float4*)&A[(size_t)(row0 + r) * K + k0 + c4];
            As[c4 + 0][r] = v.x; As[c4 + 1][r] = v.y;
            As[c4 + 2][r] = v.z; As[c4 + 3][r] = v.w;
        }
        // B tile 16x128 -> Bs[k][n]
        #pragma unroll
        for (int it = 0; it < 2; it++) {
            int idx = tid + it * 256;
            int r   = idx >> 5;
            int c4  = (idx & 31) * 4;
            *(float4*)&Bs[r][c4] = *(const float4*)&B[(size_t)(k0 + r) * N + col0 + c4];
        }
        __syncthreads();

        #pragma unroll
        for (int k = 0; k < BK; k++) {
            float a[8], bx[8];
            *(float4*)&a[0]  = *(float4*)&As[k][tm0];
            *(float4*)&a[4]  = *(float4*)&As[k][tm0 + 4];
            *(float4*)&bx[0] = *(float4*)&Bs[k][tn0];
            *(float4*)&bx[4] = *(float4*)&Bs[k][tn0 + 4];
            #pragma unroll
            for (int i = 0; i < 8; i++)
                #pragma unroll
                for (int j = 0; j < 8; j++)
                    acc[i][j] += a[i] * bx[j];
        }
        __syncthreads();
    }

    #pragma unroll
    for (int i = 0; i < 8; i++) {
        const size_t m = row0 + tm0 + i;
        #pragma unroll
        for (int j = 0; j < 8; j++) {
            const size_t n = col0 + tn0 + j;
            float v = acc[i][j];
            if (bias)    v += bias[n];
            if (do_gelu) v = 0.5f * v * (1.f + erff(v * 0.70710678118654752f));
            if (resid)   v += resid[m * N + n];
            C[m * N + n] = v;
        }
    }
}

// ---------------------------------------------------------------------------
// Flash attention, fp32, D=64. Br=64 queries/block, Bc=32 keys/iter.
// qkv layout: row (b*NN+n), col = part*CC + h*DD + d, row stride 3*CC
// grid: (NN/64, BB*HH), 256 threads
// ---------------------------------------------------------------------------
__global__ __launch_bounds__(256) void attn_kernel(
    const float* __restrict__ qkv, float* __restrict__ o)
{
    __shared__ float Qs[64][64];
    __shared__ float Kt[64][32];   // [d][j]
    __shared__ float Vs[32][64];   // [j][d]
    __shared__ float Ps[64][32];   // [i][j]

    const int tid = threadIdx.x;
    const int b   = blockIdx.y >> 4;
    const int h   = blockIdx.y & 15;
    const int q0  = blockIdx.x * 64;
    const size_t rs = 3 * CC;
    const float* base = qkv + (size_t)b * NN * rs;
    const int qcol = h * DD;

    // load Q tile (64x64)
    #pragma unroll
    for (int it = 0; it < 4; it++) {
        int idx = tid + it * 256;
        int r   = idx >> 4;
        int c4  = (idx & 15) * 4;
        *(float4*)&Qs[r][c4] =
            *(const float4*)&base[(size_t)(q0 + r) * rs + qcol + c4];
    }

    const int i    = tid >> 2;      // query row 0..63
    const int quad = tid & 3;
    const int j0   = quad * 8;      // S columns owned
    const int c0   = quad * 16;     // O columns owned

    float m_i = -1e30f, l_i = 0.f;
    float Oacc[16];
    #pragma unroll
    for (int cc = 0; cc < 16; cc++) Oacc[cc] = 0.f;

    for (int k0 = 0; k0 < NN; k0 += 32) {
        __syncthreads();   // previous iter's Ps/Vs reads done; Q visible on 1st iter
        // load K (transposed) and V tiles (32 rows each)
        #pragma unroll
        for (int it = 0; it < 2; it++) {
            int idx = tid + it * 256;
            int r   = idx >> 4;
            int c4  = (idx & 15) * 4;
            float4 kv = *(const float4*)&base[(size_t)(k0 + r) * rs + CC + qcol + c4];
            Kt[c4 + 0][r] = kv.x; Kt[c4 + 1][r] = kv.y;
            Kt[c4 + 2][r] = kv.z; Kt[c4 + 3][r] = kv.w;
            *(float4*)&Vs[r][c4] =
                *(const float4*)&base[(size_t)(k0 + r) * rs + 2 * CC + qcol + c4];
        }
        __syncthreads();

        // S = (Q K^T) * scale : each thread 8 columns of its row
        float s[8];
        #pragma unroll
        for (int jj = 0; jj < 8; jj++) s[jj] = 0.f;
        #pragma unroll 4
        for (int d = 0; d < 64; d++) {
            float qv  = Qs[i][d];
            float4 kA = *(float4*)&Kt[d][j0];
            float4 kB = *(float4*)&Kt[d][j0 + 4];
            s[0] += qv * kA.x; s[1] += qv * kA.y; s[2] += qv * kA.z; s[3] += qv * kA.w;
            s[4] += qv * kB.x; s[5] += qv * kB.y; s[6] += qv * kB.z; s[7] += qv * kB.w;
        }
        float mt = -1e30f;
        #pragma unroll
        for (int jj = 0; jj < 8; jj++) { s[jj] *= 0.125f; mt = fmaxf(mt, s[jj]); }
        mt = fmaxf(mt, __shfl_xor_sync(0xffffffffu, mt, 1));
        mt = fmaxf(mt, __shfl_xor_sync(0xffffffffu, mt, 2));
        const float m_new = fmaxf(m_i, mt);
        const float alpha = __expf(m_i - m_new);

        float p[8], rsum = 0.f;
        #pragma unroll
        for (int jj = 0; jj < 8; jj++) { p[jj] = __expf(s[jj] - m_new); rsum += p[jj]; }
        rsum += __shfl_xor_sync(0xffffffffu, rsum, 1);
        rsum += __shfl_xor_sync(0xffffffffu, rsum, 2);
        l_i = l_i * alpha + rsum;
        m_i = m_new;
        #pragma unroll
        for (int cc = 0; cc < 16; cc++) Oacc[cc] *= alpha;

        *(float4*)&Ps[i][j0]     = make_float4(p[0], p[1], p[2], p[3]);
        *(float4*)&Ps[i][j0 + 4] = make_float4(p[4], p[5], p[6], p[7]);
        __syncthreads();

        // O += P @ V : each thread 16 d-columns of its row
        #pragma unroll 4
        for (int j = 0; j < 32; j++) {
            float pv  = Ps[i][j];
            float4 vA = *(float4*)&Vs[j][c0];
            float4 vB = *(float4*)&Vs[j][c0 + 4];
            float4 vC = *(float4*)&Vs[j][c0 + 8];
            float4 vD = *(float4*)&Vs[j][c0 + 12];
            Oacc[0]  += pv * vA.x; Oacc[1]  += pv * vA.y; Oacc[2]  += pv * vA.z; Oacc[3]  += pv * vA.w;
            Oacc[4]  += pv * vB.x; Oacc[5]  += pv * vB.y; Oacc[6]  += pv * vB.z; Oacc[7]  += pv * vB.w;
            Oacc[8]  += pv * vC.x; Oacc[9]  += pv * vC.y; Oacc[10] += pv * vC.z; Oacc[11] += pv * vC.w;
            Oacc[12] += pv * vD.x; Oacc[13] += pv * vD.y; Oacc[14] += pv * vD.z; Oacc[15] += pv * vD.w;
        }
    }

    const float invl = 1.f / l_i;
    #pragma unroll
    for (int cc = 0; cc < 16; cc++) Oacc[cc] *= invl;
    float* orow = o + ((size_t)(b * NN + q0 + i)) * CC + h * DD + c0;
    *(float4*)&orow[0]  = make_float4(Oacc[0],  Oacc[1],  Oacc[2],  Oacc[3]);
    *(float4*)&orow[4]  = make_float4(Oacc[4],  Oacc[5],  Oacc[6],  Oacc[7]);
    *(float4*)&orow[8]  = make_float4(Oacc[8],  Oacc[9],  Oacc[10], Oacc[11]);
    *(float4*)&orow[12] = make_float4(Oacc[12], Oacc[13], Oacc[14], Oacc[15]);
}

// ---------------------------------------------------------------------------
// Launch
// ---------------------------------------------------------------------------
extern "C" void kernel_launch(void* const* d_in, const int* in_sizes, int n_in,
                              void* d_out, int out_size)
{
    const float* x     = (const float*)d_in[0];
    const float* ln1_g = (const float*)d_in[1];
    const float* ln1_b = (const float*)d_in[2];
    const float* w_qkv = (const float*)d_in[3];
    const float* w_prj = (const float*)d_in[4];
    const float* b_prj = (const float*)d_in[5];
    const float* ln2_g = (const float*)d_in[6];
    const float* ln2_b = (const float*)d_in[7];
    const float* w_fc1 = (const float*)d_in[8];
    const float* b_fc1 = (const float*)d_in[9];
    const float* w_fc2 = (const float*)d_in[10];
    const float* b_fc2 = (const float*)d_in[11];
    float* out = (float*)d_out;

    void *p_h, *p_qkv, *p_o, *p_x2, *p_h2, *p_hh;
    cudaGetSymbolAddress(&p_h,   g_h);
    cudaGetSymbolAddress(&p_qkv, g_qkv);
    cudaGetSymbolAddress(&p_o,   g_o);
    cudaGetSymbolAddress(&p_x2,  g_x2);
    cudaGetSymbolAddress(&p_h2,  g_h2);
    cudaGetSymbolAddress(&p_hh,  g_hh);
    float* h   = (float*)p_h;
    float* qkv = (float*)p_qkv;
    float* o   = (float*)p_o;
    float* x2  = (float*)p_x2;
    float* h2  = (float*)p_h2;
    float* hh  = (float*)p_hh;

    // 1. LN1
    ln_kernel<<<MROWS, 256>>>(x, ln1_g, ln1_b, h);
    // 2. qkv = h @ w_qkv              [4096 x 3072], no bias
    gemm_kernel<<<dim3(3 * CC / BN, MROWS / BM), 256>>>(
        h, w_qkv, nullptr, nullptr, qkv, MROWS, 3 * CC, CC, 0);
    // 3. attention
    attn_kernel<<<dim3(NN / 64, BB * HH), 256>>>(qkv, o);
    // 4. x2 = x + o @ w_prj + b_prj   [4096 x 1024]
    gemm_kernel<<<dim3(CC / BN, MROWS / BM), 256>>>(
        o, w_prj, b_prj, x, x2, MROWS, CC, CC, 0);
    // 5. LN2
    ln_kernel<<<MROWS, 256>>>(x2, ln2_g, ln2_b, h2);
    // 6. hh = gelu(h2 @ w_fc1 + b_fc1) [4096 x 4096]
    gemm_kernel<<<dim3(HID / BN, MROWS / BM), 256>>>(
        h2, w_fc1, b_fc1, nullptr, hh, MROWS, HID, CC, 1);
    // 7. out = x2 + hh @ w_fc2 + b_fc2 [4096 x 1024]
    gemm_kernel<<<dim3(CC / BN, MROWS / BM), 256>>>(
        hh, w_fc2, b_fc2, x2, out, MROWS, CC, HID, 0);
}

// round 3
// speedup vs baseline: 1.3237x; 1.3237x over previous
#include <cuda_runtime.h>
#include <cuda_bf16.h>
#include <cstdint>
#include <math.h>

// Problem dims (fixed by the reference)
#define BB    2
#define NN    2048
#define CC    1024
#define HH    16
#define DD    64
#define HID   4096
#define MROWS (BB * NN)          // 4096

// ---------------------------------------------------------------------------
// Scratch (device globals; no allocation allowed)
// ---------------------------------------------------------------------------
__device__ __align__(16) float          g_qkv[MROWS * 3 * CC];      // qkv fp32
__device__ __align__(16) float          g_o  [MROWS * CC];          // attention out
__device__ __align__(16) float          g_x2 [MROWS * CC];          // x + proj
__device__ __align__(16) __nv_bfloat16  g_a3 [MROWS * 3 * CC];      // A hi/lo/hi
__device__ __align__(16) __nv_bfloat16  g_hh3[MROWS * 3 * HID];     // fc1 out hi/lo/hi
__device__ __align__(16) __nv_bfloat16  g_b3 [MROWS * 3 * CC];      // Bt hi/hi/lo (reused)

// ---------------------------------------------------------------------------
// mma.sync helpers (sm_80+ PTX; works on sm_100 plain target)
// ---------------------------------------------------------------------------
__device__ __forceinline__ void mma_bf16(float* c, const uint32_t* a, const uint32_t* b) {
    asm volatile(
        "mma.sync.aligned.m16n8k16.row.col.f32.bf16.bf16.f32 "
        "{%0,%1,%2,%3}, {%4,%5,%6,%7}, {%8,%9}, {%0,%1,%2,%3};"
        : "+f"(c[0]), "+f"(c[1]), "+f"(c[2]), "+f"(c[3])
        : "r"(a[0]), "r"(a[1]), "r"(a[2]), "r"(a[3]), "r"(b[0]), "r"(b[1]));
}
__device__ __forceinline__ void ldsm_x4(uint32_t* r, uint32_t addr) {
    asm volatile("ldmatrix.sync.aligned.m8n8.x4.shared.b16 {%0,%1,%2,%3}, [%4];"
        : "=r"(r[0]), "=r"(r[1]), "=r"(r[2]), "=r"(r[3]) : "r"(addr));
}
__device__ __forceinline__ uint32_t smem_u32(const void* p) {
    return (uint32_t)__cvta_generic_to_shared(p);
}

// ---------------------------------------------------------------------------
// hi/lo split helpers: x = hi + lo (bf16 each)
// ---------------------------------------------------------------------------
__device__ __forceinline__ void hilo(float x, unsigned short& h, unsigned short& l) {
    __nv_bfloat16 hb = __float2bfloat16_rn(x);
    float r = x - __bfloat162float(hb);
    __nv_bfloat16 lb = __float2bfloat16_rn(r);
    h = __bfloat16_as_ushort(hb);
    l = __bfloat16_as_ushort(lb);
}

// ---------------------------------------------------------------------------
// LayerNorm fused with hi/lo/hi output: one block per row of 1024
// out row layout (stride 3*CC bf16): [hi(1024) | lo(1024) | hi(1024)]
// ---------------------------------------------------------------------------
__global__ __launch_bounds__(256) void ln_hilo_kernel(
    const float* __restrict__ x, const float* __restrict__ g,
    const float* __restrict__ b, __nv_bfloat16* __restrict__ y)
{
    __shared__ float red[16];
    const int row = blockIdx.x;
    const int tid = threadIdx.x;
    const float* xr = x + (size_t)row * CC;

    float4 xv = *(const float4*)&xr[tid * 4];
    float s  = xv.x + xv.y + xv.z + xv.w;
    float s2 = xv.x*xv.x + xv.y*xv.y + xv.z*xv.z + xv.w*xv.w;
    #pragma unroll
    for (int o = 16; o > 0; o >>= 1) {
        s  += __shfl_xor_sync(0xffffffffu, s,  o);
        s2 += __shfl_xor_sync(0xffffffffu, s2, o);
    }
    const int warp = tid >> 5;
    if ((tid & 31) == 0) { red[warp] = s; red[warp + 8] = s2; }
    __syncthreads();
    if (tid < 32) {
        float a  = (tid < 8) ? red[tid]     : 0.f;
        float a2 = (tid < 8) ? red[tid + 8] : 0.f;
        #pragma unroll
        for (int o = 4; o > 0; o >>= 1) {
            a  += __shfl_xor_sync(0xffffffffu, a,  o);
            a2 += __shfl_xor_sync(0xffffffffu, a2, o);
        }
        if (tid == 0) { red[0] = a; red[1] = a2; }
    }
    __syncthreads();

    const float mean = red[0] * (1.f / CC);
    const float var  = red[1] * (1.f / CC) - mean * mean;
    const float inv  = rsqrtf(var + 1e-5f);

    float4 gv = *(const float4*)&g[tid * 4];
    float4 bv = *(const float4*)&b[tid * 4];
    float yv[4];
    yv[0] = (xv.x - mean) * inv * gv.x + bv.x;
    yv[1] = (xv.y - mean) * inv * gv.y + bv.y;
    yv[2] = (xv.z - mean) * inv * gv.z + bv.z;
    yv[3] = (xv.w - mean) * inv * gv.w + bv.w;

    ushort4 h4, l4;
    hilo(yv[0], h4.x, l4.x); hilo(yv[1], h4.y, l4.y);
    hilo(yv[2], h4.z, l4.z); hilo(yv[3], h4.w, l4.w);

    __nv_bfloat16* yr = y + (size_t)row * (3 * CC);
    *(ushort4*)&yr[tid * 4]           = h4;
    *(ushort4*)&yr[CC + tid * 4]      = l4;
    *(ushort4*)&yr[2 * CC + tid * 4]  = h4;
}

// ---------------------------------------------------------------------------
// fp32 [M,1024] -> hi/lo/hi bf16 [M, 3072]   (one block per row)
// ---------------------------------------------------------------------------
__global__ __launch_bounds__(256) void conv_a_kernel(
    const float* __restrict__ x, __nv_bfloat16* __restrict__ y)
{
    const int row = blockIdx.x;
    const int tid = threadIdx.x;
    float4 v = *(const float4*)&x[(size_t)row * CC + tid * 4];
    ushort4 h4, l4;
    hilo(v.x, h4.x, l4.x); hilo(v.y, h4.y, l4.y);
    hilo(v.z, h4.z, l4.z); hilo(v.w, h4.w, l4.w);
    __nv_bfloat16* yr = y + (size_t)row * (3 * CC);
    *(ushort4*)&yr[tid * 4]          = h4;
    *(ushort4*)&yr[CC + tid * 4]     = l4;
    *(ushort4*)&yr[2 * CC + tid * 4] = h4;
}

// ---------------------------------------------------------------------------
// Weight convert + transpose: W[K,N] fp32 -> Bt3[N, 3K] bf16, row n = [hi|hi|lo]
// grid (N/32, K/32), 256 threads (32x8)
// ---------------------------------------------------------------------------
__global__ __launch_bounds__(256) void conv_b_kernel(
    const float* __restrict__ W, __nv_bfloat16* __restrict__ Y, int K, int N)
{
    __shared__ float t[32][33];
    const int nb = blockIdx.x * 32, kb = blockIdx.y * 32;
    const int tx = threadIdx.x & 31, ty = threadIdx.x >> 5;
    #pragma unroll
    for (int j = 0; j < 32; j += 8)
        t[ty + j][tx] = W[(size_t)(kb + ty + j) * N + nb + tx];
    __syncthreads();
    #pragma unroll
    for (int j = 0; j < 32; j += 8) {
        const int n = nb + ty + j, k = kb + tx;
        unsigned short h, l;
        hilo(t[tx][ty + j], h, l);
        __nv_bfloat16* yr = Y + (size_t)n * (3 * K);
        yr[k]         = __ushort_as_bfloat16(h);
        yr[K + k]     = __ushort_as_bfloat16(h);
        yr[2 * K + k] = __ushort_as_bfloat16(l);
    }
}

// ---------------------------------------------------------------------------
// mma.sync bf16 GEMM: C[M,N] = epi( A[M,Kp] @ Bt[N,Kp]^T )
// 128x128 block, BK=32, 8 warps (2 m x 4 n), warp tile 64x32.
// out_hilo: C is bf16 [M, 3N] hi/lo/hi (with gelu), else fp32 [M,N].
// ---------------------------------------------------------------------------
#define BKG 32
#define LDS_STRIDE 40    // 32 + 8 pad (80B rows: ldmatrix conflict-free)

__global__ __launch_bounds__(256) void mma_gemm(
    const __nv_bfloat16* __restrict__ A, const __nv_bfloat16* __restrict__ Bt,
    const float* __restrict__ bias, const float* __restrict__ resid,
    void* __restrict__ Cout, int M, int N, int Kp, int do_gelu, int out_hilo)
{
    __shared__ __nv_bfloat16 As[128][LDS_STRIDE];
    __shared__ __nv_bfloat16 Bs[128][LDS_STRIDE];

    const int tid  = threadIdx.x;
    const int wid  = tid >> 5;
    const int lane = tid & 31;
    const int row0 = blockIdx.y * 128;
    const int col0 = blockIdx.x * 128;
    const int wm   = (wid & 1) * 64;       // warp m offset
    const int wn   = (wid >> 1) * 32;      // warp n offset
    const int g    = lane >> 2;
    const int tig  = lane & 3;

    float acc[4][4][4];
    #pragma unroll
    for (int mi = 0; mi < 4; mi++)
        #pragma unroll
        for (int ni = 0; ni < 4; ni++)
            #pragma unroll
            for (int c = 0; c < 4; c++) acc[mi][ni][c] = 0.f;

    // precompute ldmatrix smem addresses (constant across k0 except ks term)
    const int a_r = lane & 15;
    const int a_c = (lane >> 4) * 8;
    const int b_r = (lane & 7) + ((lane >> 4) & 1) * 8;
    const int b_c = ((lane >> 3) & 1) * 8;

    for (int k0 = 0; k0 < Kp; k0 += BKG) {
        __syncthreads();
        #pragma unroll
        for (int it = 0; it < 2; it++) {
            int idx = tid + it * 256;
            int r = idx >> 2, c = (idx & 3) * 8;
            *(uint4*)&As[r][c] = *(const uint4*)&A [(size_t)(row0 + r) * Kp + k0 + c];
        }
        #pragma unroll
        for (int it = 0; it < 2; it++) {
            int idx = tid + it * 256;
            int r = idx >> 2, c = (idx & 3) * 8;
            *(uint4*)&Bs[r][c] = *(const uint4*)&Bt[(size_t)(col0 + r) * Kp + k0 + c];
        }
        __syncthreads();

        #pragma unroll
        for (int ks = 0; ks < 2; ks++) {
            uint32_t a[4][4], b[4][2];
            #pragma unroll
            for (int mi = 0; mi < 4; mi++)
                ldsm_x4(a[mi], smem_u32(&As[wm + mi * 16 + a_r][ks * 16 + a_c]));
            #pragma unroll
            for (int np = 0; np < 2; np++) {
                uint32_t r[4];
                ldsm_x4(r, smem_u32(&Bs[wn + np * 16 + b_r][ks * 16 + b_c]));
                b[np * 2][0]     = r[0]; b[np * 2][1]     = r[1];
                b[np * 2 + 1][0] = r[2]; b[np * 2 + 1][1] = r[3];
            }
            #pragma unroll
            for (int mi = 0; mi < 4; mi++)
                #pragma unroll
                for (int ni = 0; ni < 4; ni++)
                    mma_bf16(acc[mi][ni], a[mi], b[ni]);
        }
    }

    // epilogue: frag (mi,ni): rows wm+mi*16+g (+8), cols wn+ni*8+2*tig (+1)
    #pragma unroll
    for (int mi = 0; mi < 4; mi++) {
        #pragma unroll
        for (int ni = 0; ni < 4; ni++) {
            const int bc = col0 + wn + ni * 8 + 2 * tig;
            float bx = 0.f, by = 0.f;
            if (bias) { bx = __ldg(&bias[bc]); by = __ldg(&bias[bc + 1]); }
            #pragma unroll
            for (int half = 0; half < 2; half++) {
                const int br = row0 + wm + mi * 16 + g + half * 8;
                float v0 = acc[mi][ni][half * 2 + 0] + bx;
                float v1 = acc[mi][ni][half * 2 + 1] + by;
                if (do_gelu) {
                    v0 = 0.5f * v0 * (1.f + erff(v0 * 0.70710678118654752f));
                    v1 = 0.5f * v1 * (1.f + erff(v1 * 0.70710678118654752f));
                }
                if (out_hilo) {
                    __nv_bfloat16* yr = (__nv_bfloat16*)Cout + (size_t)br * (3 * N) + bc;
                    unsigned short h0, l0, h1, l1;
                    hilo(v0, h0, l0); hilo(v1, h1, l1);
                    ushort2 hh = make_ushort2(h0, h1), ll = make_ushort2(l0, l1);
                    *(ushort2*)&yr[0]     = hh;
                    *(ushort2*)&yr[N]     = ll;
                    *(ushort2*)&yr[2 * N] = hh;
                } else {
                    float* cr = (float*)Cout + (size_t)br * N + bc;
                    if (resid) {
                        float2 rv = *(const float2*)&resid[(size_t)br * N + bc];
                        v0 += rv.x; v1 += rv.y;
                    }
                    *(float2*)cr = make_float2(v0, v1);
                }
            }
        }
    }
}

// ---------------------------------------------------------------------------
// Flash attention, fp32, D=64. Br=64 queries/block, Bc=32 keys/iter.
// qkv layout: row (b*NN+n), col = part*CC + h*DD + d, row stride 3*CC
// grid: (NN/64, BB*HH), 256 threads.  Qs/Ps padded to kill bank conflicts.
// ---------------------------------------------------------------------------
__global__ __launch_bounds__(256) void attn_kernel(
    const float* __restrict__ qkv, float* __restrict__ o)
{
    __shared__ float Qs[64][68];
    __shared__ float Kt[64][32];   // [d][j]
    __shared__ float Vs[32][64];   // [j][d]
    __shared__ float Ps[64][36];   // [i][j]

    const int tid = threadIdx.x;
    const int b   = blockIdx.y >> 4;
    const int h   = blockIdx.y & 15;
    const int q0  = blockIdx.x * 64;
    const size_t rs = 3 * CC;
    const float* base = qkv + (size_t)b * NN * rs;
    const int qcol = h * DD;

    #pragma unroll
    for (int it = 0; it < 4; it++) {
        int idx = tid + it * 256;
        int r   = idx >> 4;
        int c4  = (idx & 15) * 4;
        *(float4*)&Qs[r][c4] =
            *(const float4*)&base[(size_t)(q0 + r) * rs + qcol + c4];
    }

    const int i    = tid >> 2;
    const int quad = tid & 3;
    const int j0   = quad * 8;
    const int c0   = quad * 16;

    float m_i = -1e30f, l_i = 0.f;
    float Oacc[16];
    #pragma unroll
    for (int cc = 0; cc < 16; cc++) Oacc[cc] = 0.f;

    for (int k0 = 0; k0 < NN; k0 += 32) {
        __syncthreads();
        #pragma unroll
        for (int it = 0; it < 2; it++) {
            int idx = tid + it * 256;
            int r   = idx >> 4;
            int c4  = (idx & 15) * 4;
            float4 kv = *(const float4*)&base[(size_t)(k0 + r) * rs + CC + qcol + c4];
            Kt[c4 + 0][r] = kv.x; Kt[c4 + 1][r] = kv.y;
            Kt[c4 + 2][r] = kv.z; Kt[c4 + 3][r] = kv.w;
            *(float4*)&Vs[r][c4] =
                *(const float4*)&base[(size_t)(k0 + r) * rs + 2 * CC + qcol + c4];
        }
        __syncthreads();

        float s[8];
        #pragma unroll
        for (int jj = 0; jj < 8; jj++) s[jj] = 0.f;
        #pragma unroll 4
        for (int d = 0; d < 64; d++) {
            float qv  = Qs[i][d];
            float4 kA = *(float4*)&Kt[d][j0];
            float4 kB = *(float4*)&Kt[d][j0 + 4];
            s[0] += qv * kA.x; s[1] += qv * kA.y; s[2] += qv * kA.z; s[3] += qv * kA.w;
            s[4] += qv * kB.x; s[5] += qv * kB.y; s[6] += qv * kB.z; s[7] += qv * kB.w;
        }
        float mt = -1e30f;
        #pragma unroll
        for (int jj = 0; jj < 8; jj++) { s[jj] *= 0.125f; mt = fmaxf(mt, s[jj]); }
        mt = fmaxf(mt, __shfl_xor_sync(0xffffffffu, mt, 1));
        mt = fmaxf(mt, __shfl_xor_sync(0xffffffffu, mt, 2));
        const float m_new = fmaxf(m_i, mt);
        const float alpha = __expf(m_i - m_new);

        float p[8], rsum = 0.f;
        #pragma unroll
        for (int jj = 0; jj < 8; jj++) { p[jj] = __expf(s[jj] - m_new); rsum += p[jj]; }
        rsum += __shfl_xor_sync(0xffffffffu, rsum, 1);
        rsum += __shfl_xor_sync(0xffffffffu, rsum, 2);
        l_i = l_i * alpha + rsum;
        m_i = m_new;
        #pragma unroll
        for (int cc = 0; cc < 16; cc++) Oacc[cc] *= alpha;

        *(float4*)&Ps[i][j0]     = make_float4(p[0], p[1], p[2], p[3]);
        *(float4*)&Ps[i][j0 + 4] = make_float4(p[4], p[5], p[6], p[7]);
        __syncthreads();

        #pragma unroll 4
        for (int j = 0; j < 32; j++) {
            float pv  = Ps[i][j];
            float4 vA = *(float4*)&Vs[j][c0];
            float4 vB = *(float4*)&Vs[j][c0 + 4];
            float4 vC = *(float4*)&Vs[j][c0 + 8];
            float4 vD = *(float4*)&Vs[j][c0 + 12];
            Oacc[0]  += pv * vA.x; Oacc[1]  += pv * vA.y; Oacc[2]  += pv * vA.z; Oacc[3]  += pv * vA.w;
            Oacc[4]  += pv * vB.x; Oacc[5]  += pv * vB.y; Oacc[6]  += pv * vB.z; Oacc[7]  += pv * vB.w;
            Oacc[8]  += pv * vC.x; Oacc[9]  += pv * vC.y; Oacc[10] += pv * vC.z; Oacc[11] += pv * vC.w;
            Oacc[12] += pv * vD.x; Oacc[13] += pv * vD.y; Oacc[14] += pv * vD.z; Oacc[15] += pv * vD.w;
        }
    }

    const float invl = 1.f / l_i;
    #pragma unroll
    for (int cc = 0; cc < 16; cc++) Oacc[cc] *= invl;
    float* orow = o + ((size_t)(b * NN + q0 + i)) * CC + h * DD + c0;
    *(float4*)&orow[0]  = make_float4(Oacc[0],  Oacc[1],  Oacc[2],  Oacc[3]);
    *(float4*)&orow[4]  = make_float4(Oacc[4],  Oacc[5],  Oacc[6],  Oacc[7]);
    *(float4*)&orow[8]  = make_float4(Oacc[8],  Oacc[9],  Oacc[10], Oacc[11]);
    *(float4*)&orow[12] = make_float4(Oacc[12], Oacc[13], Oacc[14], Oacc[15]);
}

// ---------------------------------------------------------------------------
// Launch
// ---------------------------------------------------------------------------
extern "C" void kernel_launch(void* const* d_in, const int* in_sizes, int n_in,
                              void* d_out, int out_size)
{
    const float* x     = (const float*)d_in[0];
    const float* ln1_g = (const float*)d_in[1];
    const float* ln1_b = (const float*)d_in[2];
    const float* w_qkv = (const float*)d_in[3];
    const float* w_prj = (const float*)d_in[4];
    const float* b_prj = (const float*)d_in[5];
    const float* ln2_g = (const float*)d_in[6];
    const float* ln2_b = (const float*)d_in[7];
    const float* w_fc1 = (const float*)d_in[8];
    const float* b_fc1 = (const float*)d_in[9];
    const float* w_fc2 = (const float*)d_in[10];
    const float* b_fc2 = (const float*)d_in[11];
    float* out = (float*)d_out;

    void *p_qkv, *p_o, *p_x2, *p_a3, *p_hh3, *p_b3;
    cudaGetSymbolAddress(&p_qkv, g_qkv);
    cudaGetSymbolAddress(&p_o,   g_o);
    cudaGetSymbolAddress(&p_x2,  g_x2);
    cudaGetSymbolAddress(&p_a3,  g_a3);
    cudaGetSymbolAddress(&p_hh3, g_hh3);
    cudaGetSymbolAddress(&p_b3,  g_b3);
    float* qkv = (float*)p_qkv;
    float* o   = (float*)p_o;
    float* x2  = (float*)p_x2;
    __nv_bfloat16* a3  = (__nv_bfloat16*)p_a3;
    __nv_bfloat16* hh3 = (__nv_bfloat16*)p_hh3;
    __nv_bfloat16* b3  = (__nv_bfloat16*)p_b3;

    // 1. LN1 -> a3 (hi/lo/hi)
    ln_hilo_kernel<<<MROWS, 256>>>(x, ln1_g, ln1_b, a3);
    // 2. w_qkv -> b3 (transposed hi/hi/lo)
    conv_b_kernel<<<dim3(3 * CC / 32, CC / 32), 256>>>(w_qkv, b3, CC, 3 * CC);
    // 3. qkv = a3 @ b3^T   [4096 x 3072], fp32 out
    mma_gemm<<<dim3(3 * CC / 128, MROWS / 128), 256>>>(
        a3, b3, nullptr, nullptr, qkv, MROWS, 3 * CC, 3 * CC, 0, 0);
    // 4. attention
    attn_kernel<<<dim3(NN / 64, BB * HH), 256>>>(qkv, o);
    // 5. o -> a3
    conv_a_kernel<<<MROWS, 256>>>(o, a3);
    // 6. w_prj -> b3
    conv_b_kernel<<<dim3(CC / 32, CC / 32), 256>>>(w_prj, b3, CC, CC);
    // 7. x2 = x + a3 @ b3^T + b_prj   [4096 x 1024], fp32 out
    mma_gemm<<<dim3(CC / 128, MROWS / 128), 256>>>(
        a3, b3, b_prj, x, x2, MROWS, CC, 3 * CC, 0, 0);
    // 8. LN2 -> a3
    ln_hilo_kernel<<<MROWS, 256>>>(x2, ln2_g, ln2_b, a3);
    // 9. w_fc1 -> b3
    conv_b_kernel<<<dim3(HID / 32, CC / 32), 256>>>(w_fc1, b3, CC, HID);
    // 10. hh3 = hilo(gelu(a3 @ b3^T + b_fc1))  [4096 x 4096] -> bf16 [4096 x 12288]
    mma_gemm<<<dim3(HID / 128, MROWS / 128), 256>>>(
        a3, b3, b_fc1, nullptr, hh3, MROWS, HID, 3 * CC, 1, 1);
    // 11. w_fc2 -> b3
    conv_b_kernel<<<dim3(CC / 32, HID / 32), 256>>>(w_fc2, b3, HID, CC);
    // 12. out = x2 + hh3 @ b3^T + b_fc2   [4096 x 1024], fp32
    mma_gemm<<<dim3(CC / 128, MROWS / 128), 256>>>(
        hh3, b3, b_fc2, x2, out, MROWS, CC, 3 * HID, 0, 0);
}

// round 4
// speedup vs baseline: 3.5876x; 2.7104x over previous
#include <cuda_runtime.h>
#include <cuda_bf16.h>
#include <cstdint>
#include <math.h>

// Problem dims (fixed by the reference)
#define BB    2
#define NN    2048
#define CC    1024
#define HH    16
#define DD    64
#define HID   4096
#define MROWS (BB * NN)          // 4096

// ---------------------------------------------------------------------------
// Scratch (device globals; no allocation allowed)
// ---------------------------------------------------------------------------
__device__ __align__(16) __nv_bfloat16  g_qkvh[MROWS * 3 * CC];     // qkv bf16
__device__ __align__(16) float          g_o  [MROWS * CC];          // attention out
__device__ __align__(16) float          g_x2 [MROWS * CC];          // x + proj
__device__ __align__(16) __nv_bfloat16  g_a3 [MROWS * 3 * CC];      // A hi/lo/hi
__device__ __align__(16) __nv_bfloat16  g_hh3[MROWS * 3 * HID];     // fc1 out hi/lo/hi
__device__ __align__(16) __nv_bfloat16  g_b3 [MROWS * 3 * CC];      // Bt hi/hi/lo (reused)

// ---------------------------------------------------------------------------
// mma.sync helpers (sm_80+ PTX)
// ---------------------------------------------------------------------------
__device__ __forceinline__ void mma_bf16(float* c, const uint32_t* a, const uint32_t* b) {
    asm volatile(
        "mma.sync.aligned.m16n8k16.row.col.f32.bf16.bf16.f32 "
        "{%0,%1,%2,%3}, {%4,%5,%6,%7}, {%8,%9}, {%0,%1,%2,%3};"
        : "+f"(c[0]), "+f"(c[1]), "+f"(c[2]), "+f"(c[3])
        : "r"(a[0]), "r"(a[1]), "r"(a[2]), "r"(a[3]), "r"(b[0]), "r"(b[1]));
}
__device__ __forceinline__ void ldsm_x4(uint32_t* r, uint32_t addr) {
    asm volatile("ldmatrix.sync.aligned.m8n8.x4.shared.b16 {%0,%1,%2,%3}, [%4];"
        : "=r"(r[0]), "=r"(r[1]), "=r"(r[2]), "=r"(r[3]) : "r"(addr));
}
__device__ __forceinline__ void ldsm_x4_t(uint32_t* r, uint32_t addr) {
    asm volatile("ldmatrix.sync.aligned.m8n8.x4.trans.shared.b16 {%0,%1,%2,%3}, [%4];"
        : "=r"(r[0]), "=r"(r[1]), "=r"(r[2]), "=r"(r[3]) : "r"(addr));
}
__device__ __forceinline__ uint32_t smem_u32(const void* p) {
    return (uint32_t)__cvta_generic_to_shared(p);
}
// pack two f32 -> bf16x2 (lo = first arg in low half)
__device__ __forceinline__ uint32_t packbf(float lo, float hi) {
    uint32_t r;
    asm("cvt.rn.bf16x2.f32 %0, %1, %2;" : "=r"(r) : "f"(hi), "f"(lo));
    return r;
}

// ---------------------------------------------------------------------------
// hi/lo split helpers: x = hi + lo (bf16 each)
// ---------------------------------------------------------------------------
__device__ __forceinline__ void hilo(float x, unsigned short& h, unsigned short& l) {
    __nv_bfloat16 hb = __float2bfloat16_rn(x);
    float r = x - __bfloat162float(hb);
    __nv_bfloat16 lb = __float2bfloat16_rn(r);
    h = __bfloat16_as_ushort(hb);
    l = __bfloat16_as_ushort(lb);
}

// ---------------------------------------------------------------------------
// LayerNorm fused with hi/lo/hi output: one block per row of 1024
// ---------------------------------------------------------------------------
__global__ __launch_bounds__(256) void ln_hilo_kernel(
    const float* __restrict__ x, const float* __restrict__ g,
    const float* __restrict__ b, __nv_bfloat16* __restrict__ y)
{
    __shared__ float red[16];
    const int row = blockIdx.x;
    const int tid = threadIdx.x;
    const float* xr = x + (size_t)row * CC;

    float4 xv = *(const float4*)&xr[tid * 4];
    float s  = xv.x + xv.y + xv.z + xv.w;
    float s2 = xv.x*xv.x + xv.y*xv.y + xv.z*xv.z + xv.w*xv.w;
    #pragma unroll
    for (int o = 16; o > 0; o >>= 1) {
        s  += __shfl_xor_sync(0xffffffffu, s,  o);
        s2 += __shfl_xor_sync(0xffffffffu, s2, o);
    }
    const int warp = tid >> 5;
    if ((tid & 31) == 0) { red[warp] = s; red[warp + 8] = s2; }
    __syncthreads();
    if (tid < 32) {
        float a  = (tid < 8) ? red[tid]     : 0.f;
        float a2 = (tid < 8) ? red[tid + 8] : 0.f;
        #pragma unroll
        for (int o = 4; o > 0; o >>= 1) {
            a  += __shfl_xor_sync(0xffffffffu, a,  o);
            a2 += __shfl_xor_sync(0xffffffffu, a2, o);
        }
        if (tid == 0) { red[0] = a; red[1] = a2; }
    }
    __syncthreads();

    const float mean = red[0] * (1.f / CC);
    const float var  = red[1] * (1.f / CC) - mean * mean;
    const float inv  = rsqrtf(var + 1e-5f);

    float4 gv = *(const float4*)&g[tid * 4];
    float4 bv = *(const float4*)&b[tid * 4];
    float yv[4];
    yv[0] = (xv.x - mean) * inv * gv.x + bv.x;
    yv[1] = (xv.y - mean) * inv * gv.y + bv.y;
    yv[2] = (xv.z - mean) * inv * gv.z + bv.z;
    yv[3] = (xv.w - mean) * inv * gv.w + bv.w;

    ushort4 h4, l4;
    hilo(yv[0], h4.x, l4.x); hilo(yv[1], h4.y, l4.y);
    hilo(yv[2], h4.z, l4.z); hilo(yv[3], h4.w, l4.w);

    __nv_bfloat16* yr = y + (size_t)row * (3 * CC);
    *(ushort4*)&yr[tid * 4]           = h4;
    *(ushort4*)&yr[CC + tid * 4]      = l4;
    *(ushort4*)&yr[2 * CC + tid * 4]  = h4;
}

// ---------------------------------------------------------------------------
// fp32 [M,1024] -> hi/lo/hi bf16 [M, 3072]   (one block per row)
// ---------------------------------------------------------------------------
__global__ __launch_bounds__(256) void conv_a_kernel(
    const float* __restrict__ x, __nv_bfloat16* __restrict__ y)
{
    const int row = blockIdx.x;
    const int tid = threadIdx.x;
    float4 v = *(const float4*)&x[(size_t)row * CC + tid * 4];
    ushort4 h4, l4;
    hilo(v.x, h4.x, l4.x); hilo(v.y, h4.y, l4.y);
    hilo(v.z, h4.z, l4.z); hilo(v.w, h4.w, l4.w);
    __nv_bfloat16* yr = y + (size_t)row * (3 * CC);
    *(ushort4*)&yr[tid * 4]          = h4;
    *(ushort4*)&yr[CC + tid * 4]     = l4;
    *(ushort4*)&yr[2 * CC + tid * 4] = h4;
}

// ---------------------------------------------------------------------------
// Weight convert + transpose: W[K,N] fp32 -> Bt3[N, 3K] bf16, row n = [hi|hi|lo]
// ---------------------------------------------------------------------------
__global__ __launch_bounds__(256) void conv_b_kernel(
    const float* __restrict__ W, __nv_bfloat16* __restrict__ Y, int K, int N)
{
    __shared__ float t[32][33];
    const int nb = blockIdx.x * 32, kb = blockIdx.y * 32;
    const int tx = threadIdx.x & 31, ty = threadIdx.x >> 5;
    #pragma unroll
    for (int j = 0; j < 32; j += 8)
        t[ty + j][tx] = W[(size_t)(kb + ty + j) * N + nb + tx];
    __syncthreads();
    #pragma unroll
    for (int j = 0; j < 32; j += 8) {
        const int n = nb + ty + j, k = kb + tx;
        unsigned short h, l;
        hilo(t[tx][ty + j], h, l);
        __nv_bfloat16* yr = Y + (size_t)n * (3 * K);
        yr[k]         = __ushort_as_bfloat16(h);
        yr[K + k]     = __ushort_as_bfloat16(h);
        yr[2 * K + k] = __ushort_as_bfloat16(l);
    }
}

// ---------------------------------------------------------------------------
// mma.sync bf16 GEMM: C[M,N] = epi( A[M,Kp] @ Bt[N,Kp]^T )
// 128x128 block, BK=32, 8 warps (2 m x 4 n), warp tile 64x32.
// out_mode: 0 = fp32 (+resid), 1 = bf16 hi/lo/hi [M,3N], 2 = plain bf16 [M,N]
// ---------------------------------------------------------------------------
#define BKG 32
#define LDS_STRIDE 40    // 32 + 8 pad

__global__ __launch_bounds__(256) void mma_gemm(
    const __nv_bfloat16* __restrict__ A, const __nv_bfloat16* __restrict__ Bt,
    const float* __restrict__ bias, const float* __restrict__ resid,
    void* __restrict__ Cout, int M, int N, int Kp, int do_gelu, int out_mode)
{
    __shared__ __nv_bfloat16 As[128][LDS_STRIDE];
    __shared__ __nv_bfloat16 Bs[128][LDS_STRIDE];

    const int tid  = threadIdx.x;
    const int wid  = tid >> 5;
    const int lane = tid & 31;
    const int row0 = blockIdx.y * 128;
    const int col0 = blockIdx.x * 128;
    const int wm   = (wid & 1) * 64;
    const int wn   = (wid >> 1) * 32;
    const int g    = lane >> 2;
    const int tig  = lane & 3;

    float acc[4][4][4];
    #pragma unroll
    for (int mi = 0; mi < 4; mi++)
        #pragma unroll
        for (int ni = 0; ni < 4; ni++)
            #pragma unroll
            for (int c = 0; c < 4; c++) acc[mi][ni][c] = 0.f;

    const int a_r = lane & 15;
    const int a_c = (lane >> 4) * 8;
    const int b_r = (lane & 7) + ((lane >> 4) & 1) * 8;
    const int b_c = ((lane >> 3) & 1) * 8;

    for (int k0 = 0; k0 < Kp; k0 += BKG) {
        __syncthreads();
        #pragma unroll
        for (int it = 0; it < 2; it++) {
            int idx = tid + it * 256;
            int r = idx >> 2, c = (idx & 3) * 8;
            *(uint4*)&As[r][c] = *(const uint4*)&A [(size_t)(row0 + r) * Kp + k0 + c];
        }
        #pragma unroll
        for (int it = 0; it < 2; it++) {
            int idx = tid + it * 256;
            int r = idx >> 2, c = (idx & 3) * 8;
            *(uint4*)&Bs[r][c] = *(const uint4*)&Bt[(size_t)(col0 + r) * Kp + k0 + c];
        }
        __syncthreads();

        #pragma unroll
        for (int ks = 0; ks < 2; ks++) {
            uint32_t a[4][4], b[4][2];
            #pragma unroll
            for (int mi = 0; mi < 4; mi++)
                ldsm_x4(a[mi], smem_u32(&As[wm + mi * 16 + a_r][ks * 16 + a_c]));
            #pragma unroll
            for (int np = 0; np < 2; np++) {
                uint32_t r[4];
                ldsm_x4(r, smem_u32(&Bs[wn + np * 16 + b_r][ks * 16 + b_c]));
                b[np * 2][0]     = r[0]; b[np * 2][1]     = r[1];
                b[np * 2 + 1][0] = r[2]; b[np * 2 + 1][1] = r[3];
            }
            #pragma unroll
            for (int mi = 0; mi < 4; mi++)
                #pragma unroll
                for (int ni = 0; ni < 4; ni++)
                    mma_bf16(acc[mi][ni], a[mi], b[ni]);
        }
    }

    #pragma unroll
    for (int mi = 0; mi < 4; mi++) {
        #pragma unroll
        for (int ni = 0; ni < 4; ni++) {
            const int bc = col0 + wn + ni * 8 + 2 * tig;
            float bx = 0.f, by = 0.f;
            if (bias) { bx = __ldg(&bias[bc]); by = __ldg(&bias[bc + 1]); }
            #pragma unroll
            for (int half = 0; half < 2; half++) {
                const int br = row0 + wm + mi * 16 + g + half * 8;
                float v0 = acc[mi][ni][half * 2 + 0] + bx;
                float v1 = acc[mi][ni][half * 2 + 1] + by;
                if (do_gelu) {
                    v0 = 0.5f * v0 * (1.f + erff(v0 * 0.70710678118654752f));
                    v1 = 0.5f * v1 * (1.f + erff(v1 * 0.70710678118654752f));
                }
                if (out_mode == 1) {
                    __nv_bfloat16* yr = (__nv_bfloat16*)Cout + (size_t)br * (3 * N) + bc;
                    unsigned short h0, l0, h1, l1;
                    hilo(v0, h0, l0); hilo(v1, h1, l1);
                    ushort2 hh = make_ushort2(h0, h1), ll = make_ushort2(l0, l1);
                    *(ushort2*)&yr[0]     = hh;
                    *(ushort2*)&yr[N]     = ll;
                    *(ushort2*)&yr[2 * N] = hh;
                } else if (out_mode == 2) {
                    __nv_bfloat16* yr = (__nv_bfloat16*)Cout + (size_t)br * N + bc;
                    ushort2 hh = make_ushort2(
                        __bfloat16_as_ushort(__float2bfloat16_rn(v0)),
                        __bfloat16_as_ushort(__float2bfloat16_rn(v1)));
                    *(ushort2*)yr = hh;
                } else {
                    float* cr = (float*)Cout + (size_t)br * N + bc;
                    if (resid) {
                        float2 rv = *(const float2*)&resid[(size_t)br * N + bc];
                        v0 += rv.x; v1 += rv.y;
                    }
                    *(float2*)cr = make_float2(v0, v1);
                }
            }
        }
    }
}

// ---------------------------------------------------------------------------
// Tensor-core flash attention (bf16 mma.sync, fp32 softmax/accum).
// CTA: 128 queries, 8 warps x 16 rows. Key blocks of 128.
// qkv (bf16) row layout: [q(1024) | k(1024) | v(1024)], row stride 3072.
// grid: (NN/128, BB*HH), 256 threads.
// ---------------------------------------------------------------------------
#define AST 72   // smem row stride (halves): 144B rows -> conflict-free ldmatrix

__global__ __launch_bounds__(256) void attn_mma(
    const __nv_bfloat16* __restrict__ qkv, float* __restrict__ o)
{
    __shared__ __nv_bfloat16 Ks[128][AST];
    __shared__ __nv_bfloat16 Vs[128][AST];

    const int tid  = threadIdx.x;
    const int wid  = tid >> 5;
    const int lane = tid & 31;
    const int b    = blockIdx.y >> 4;
    const int h    = blockIdx.y & 15;
    const int q0   = blockIdx.x * 128;
    const __nv_bfloat16* base = qkv + (size_t)b * NN * (3 * CC);
    const int qc = h * DD;

    const int g = lane >> 2;
    const int t = lane & 3;
    // ldmatrix lane address components
    const int a_r  = lane & 15;                          // A frags (Q)
    const int a_c  = (lane >> 4) * 8;
    const int kb_r = (lane & 7) + ((lane >> 4) & 1) * 8; // K B-frags (non-trans)
    const int kb_c = ((lane >> 3) & 1) * 8;
    const int vb_r = (lane & 7) + ((lane >> 3) & 1) * 8; // V B-frags (trans)
    const int vb_c = ((lane >> 4) & 1) * 8;

    // ---- load Q block into Ks, extract A fragments (held all kernel) ----
    #pragma unroll
    for (int it = 0; it < 4; it++) {
        int idx = tid + it * 256;
        int r = idx >> 3, c8 = (idx & 7) * 8;
        *(uint4*)&Ks[r][c8] = *(const uint4*)&base[(size_t)(q0 + r) * (3 * CC) + qc + c8];
    }
    __syncthreads();
    uint32_t qf[4][4];
    #pragma unroll
    for (int ks = 0; ks < 4; ks++)
        ldsm_x4(qf[ks], smem_u32(&Ks[wid * 16 + a_r][ks * 16 + a_c]));

    float m0 = -1e30f, m1 = -1e30f, l0 = 0.f, l1 = 0.f;
    float oa[8][4];
    #pragma unroll
    for (int nd = 0; nd < 8; nd++)
        #pragma unroll
        for (int c = 0; c < 4; c++) oa[nd][c] = 0.f;

    for (int k0 = 0; k0 < NN; k0 += 128) {
        __syncthreads();   // Q-frag extraction / previous iter reads done
        #pragma unroll
        for (int it = 0; it < 4; it++) {
            int idx = tid + it * 256;
            int r = idx >> 3, c8 = (idx & 7) * 8;
            const size_t gro = (size_t)(k0 + r) * (3 * CC) + qc + c8;
            *(uint4*)&Ks[r][c8] = *(const uint4*)&base[gro + CC];
            *(uint4*)&Vs[r][c8] = *(const uint4*)&base[gro + 2 * CC];
        }
        __syncthreads();

        // ---- S = Q @ K^T  (16 n-tiles of 8 seq cols) ----
        float s[16][4];
        #pragma unroll
        for (int nt = 0; nt < 16; nt++)
            #pragma unroll
            for (int c = 0; c < 4; c++) s[nt][c] = 0.f;

        #pragma unroll
        for (int ks = 0; ks < 4; ks++) {
            #pragma unroll
            for (int ntp = 0; ntp < 8; ntp++) {
                uint32_t kr[4];
                ldsm_x4(kr, smem_u32(&Ks[ntp * 16 + kb_r][ks * 16 + kb_c]));
                mma_bf16(s[2 * ntp],     qf[ks], kr);
                mma_bf16(s[2 * ntp + 1], qf[ks], kr + 2);
            }
        }

        // ---- online softmax (scale 1/8) ----
        float tm0 = -1e30f, tm1 = -1e30f;
        #pragma unroll
        for (int nt = 0; nt < 16; nt++) {
            s[nt][0] *= 0.125f; s[nt][1] *= 0.125f;
            s[nt][2] *= 0.125f; s[nt][3] *= 0.125f;
            tm0 = fmaxf(tm0, fmaxf(s[nt][0], s[nt][1]));
            tm1 = fmaxf(tm1, fmaxf(s[nt][2], s[nt][3]));
        }
        tm0 = fmaxf(tm0, __shfl_xor_sync(0xffffffffu, tm0, 1));
        tm0 = fmaxf(tm0, __shfl_xor_sync(0xffffffffu, tm0, 2));
        tm1 = fmaxf(tm1, __shfl_xor_sync(0xffffffffu, tm1, 1));
        tm1 = fmaxf(tm1, __shfl_xor_sync(0xffffffffu, tm1, 2));
        const float m0n = fmaxf(m0, tm0);
        const float m1n = fmaxf(m1, tm1);
        const float al0 = __expf(m0 - m0n);
        const float al1 = __expf(m1 - m1n);

        float r0 = 0.f, r1 = 0.f;
        #pragma unroll
        for (int nt = 0; nt < 16; nt++) {
            s[nt][0] = __expf(s[nt][0] - m0n); r0 += s[nt][0];
            s[nt][1] = __expf(s[nt][1] - m0n); r0 += s[nt][1];
            s[nt][2] = __expf(s[nt][2] - m1n); r1 += s[nt][2];
            s[nt][3] = __expf(s[nt][3] - m1n); r1 += s[nt][3];
        }
        r0 += __shfl_xor_sync(0xffffffffu, r0, 1);
        r0 += __shfl_xor_sync(0xffffffffu, r0, 2);
        r1 += __shfl_xor_sync(0xffffffffu, r1, 1);
        r1 += __shfl_xor_sync(0xffffffffu, r1, 2);
        l0 = l0 * al0 + r0;
        l1 = l1 * al1 + r1;
        m0 = m0n; m1 = m1n;
        #pragma unroll
        for (int nd = 0; nd < 8; nd++) {
            oa[nd][0] *= al0; oa[nd][1] *= al0;
            oa[nd][2] *= al1; oa[nd][3] *= al1;
        }

        // ---- P fragments (bf16) ----
        uint32_t pf[8][4];
        #pragma unroll
        for (int kt = 0; kt < 8; kt++) {
            pf[kt][0] = packbf(s[2 * kt][0],     s[2 * kt][1]);
            pf[kt][1] = packbf(s[2 * kt][2],     s[2 * kt][3]);
            pf[kt][2] = packbf(s[2 * kt + 1][0], s[2 * kt + 1][1]);
            pf[kt][3] = packbf(s[2 * kt + 1][2], s[2 * kt + 1][3]);
        }

        // ---- O += P @ V ----
        #pragma unroll
        for (int kt = 0; kt < 8; kt++) {
            #pragma unroll
            for (int ndp = 0; ndp < 4; ndp++) {
                uint32_t vr[4];
                ldsm_x4_t(vr, smem_u32(&Vs[kt * 16 + vb_r][ndp * 16 + vb_c]));
                mma_bf16(oa[2 * ndp],     pf[kt], vr);
                mma_bf16(oa[2 * ndp + 1], pf[kt], vr + 2);
            }
        }
    }

    const float inv0 = 1.f / l0;
    const float inv1 = 1.f / l1;
    const int r0w = b * NN + q0 + wid * 16 + g;
    #pragma unroll
    for (int nd = 0; nd < 8; nd++) {
        const int col = qc + nd * 8 + 2 * t;
        *(float2*)&o[(size_t)r0w * CC + col] =
            make_float2(oa[nd][0] * inv0, oa[nd][1] * inv0);
        *(float2*)&o[(size_t)(r0w + 8) * CC + col] =
            make_float2(oa[nd][2] * inv1, oa[nd][3] * inv1);
    }
}

// ---------------------------------------------------------------------------
// Launch
// ---------------------------------------------------------------------------
extern "C" void kernel_launch(void* const* d_in, const int* in_sizes, int n_in,
                              void* d_out, int out_size)
{
    const float* x     = (const float*)d_in[0];
    const float* ln1_g = (const float*)d_in[1];
    const float* ln1_b = (const float*)d_in[2];
    const float* w_qkv = (const float*)d_in[3];
    const float* w_prj = (const float*)d_in[4];
    const float* b_prj = (const float*)d_in[5];
    const float* ln2_g = (const float*)d_in[6];
    const float* ln2_b = (const float*)d_in[7];
    const float* w_fc1 = (const float*)d_in[8];
    const float* b_fc1 = (const float*)d_in[9];
    const float* w_fc2 = (const float*)d_in[10];
    const float* b_fc2 = (const float*)d_in[11];
    float* out = (float*)d_out;

    void *p_qkvh, *p_o, *p_x2, *p_a3, *p_hh3, *p_b3;
    cudaGetSymbolAddress(&p_qkvh, g_qkvh);
    cudaGetSymbolAddress(&p_o,   g_o);
    cudaGetSymbolAddress(&p_x2,  g_x2);
    cudaGetSymbolAddress(&p_a3,  g_a3);
    cudaGetSymbolAddress(&p_hh3, g_hh3);
    cudaGetSymbolAddress(&p_b3,  g_b3);
    __nv_bfloat16* qkvh = (__nv_bfloat16*)p_qkvh;
    float* o   = (float*)p_o;
    float* x2  = (float*)p_x2;
    __nv_bfloat16* a3  = (__nv_bfloat16*)p_a3;
    __nv_bfloat16* hh3 = (__nv_bfloat16*)p_hh3;
    __nv_bfloat16* b3  = (__nv_bfloat16*)p_b3;

    // 1. LN1 -> a3 (hi/lo/hi)
    ln_hilo_kernel<<<MROWS, 256>>>(x, ln1_g, ln1_b, a3);
    // 2. w_qkv -> b3 (transposed hi/hi/lo)
    conv_b_kernel<<<dim3(3 * CC / 32, CC / 32), 256>>>(w_qkv, b3, CC, 3 * CC);
    // 3. qkvh = a3 @ b3^T   [4096 x 3072], bf16 out
    mma_gemm<<<dim3(3 * CC / 128, MROWS / 128), 256>>>(
        a3, b3, nullptr, nullptr, qkvh, MROWS, 3 * CC, 3 * CC, 0, 2);
    // 4. attention (tensor core)
    attn_mma<<<dim3(NN / 128, BB * HH), 256>>>(qkvh, o);
    // 5. o -> a3
    conv_a_kernel<<<MROWS, 256>>>(o, a3);
    // 6. w_prj -> b3
    conv_b_kernel<<<dim3(CC / 32, CC / 32), 256>>>(w_prj, b3, CC, CC);
    // 7. x2 = x + a3 @ b3^T + b_prj   [4096 x 1024], fp32 out
    mma_gemm<<<dim3(CC / 128, MROWS / 128), 256>>>(
        a3, b3, b_prj, x, x2, MROWS, CC, 3 * CC, 0, 0);
    // 8. LN2 -> a3
    ln_hilo_kernel<<<MROWS, 256>>>(x2, ln2_g, ln2_b, a3);
    // 9. w_fc1 -> b3
    conv_b_kernel<<<dim3(HID / 32, CC / 32), 256>>>(w_fc1, b3, CC, HID);
    // 10. hh3 = hilo(gelu(a3 @ b3^T + b_fc1))  [4096 x 4096] -> bf16 [4096 x 12288]
    mma_gemm<<<dim3(HID / 128, MROWS / 128), 256>>>(
        a3, b3, b_fc1, nullptr, hh3, MROWS, HID, 3 * CC, 1, 1);
    // 11. w_fc2 -> b3
    conv_b_kernel<<<dim3(CC / 32, HID / 32), 256>>>(w_fc2, b3, HID, CC);
    // 12. out = x2 + hh3 @ b3^T + b_fc2   [4096 x 1024], fp32
    mma_gemm<<<dim3(CC / 128, MROWS / 128), 256>>>(
        hh3, b3, b_fc2, x2, out, MROWS, CC, 3 * HID, 0, 0);
}

// round 5
// speedup vs baseline: 4.9386x; 1.3766x over previous
#include <cuda_runtime.h>
#include <cuda_bf16.h>
#include <cstdint>
#include <math.h>

// Problem dims (fixed by the reference)
#define BB    2
#define NN    2048
#define CC    1024
#define HH    16
#define DD    64
#define HID   4096
#define MROWS (BB * NN)          // 4096

// ---------------------------------------------------------------------------
// Scratch (device globals; no allocation allowed)
// ---------------------------------------------------------------------------
__device__ __align__(16) __nv_bfloat16  g_qkvh[MROWS * 3 * CC];     // qkv bf16
__device__ __align__(16) float          g_x2 [MROWS * CC];          // x + proj
__device__ __align__(16) __nv_bfloat16  g_a3 [MROWS * 3 * CC];      // A hi/lo/hi
__device__ __align__(16) __nv_bfloat16  g_hh3[MROWS * 3 * HID];     // fc1 out hi/lo/hi
__device__ __align__(16) __nv_bfloat16  g_b3 [MROWS * 3 * CC];      // Bt hi/hi/lo (reused)

// ---------------------------------------------------------------------------
// mma.sync / cp.async helpers (sm_80+ PTX)
// ---------------------------------------------------------------------------
__device__ __forceinline__ void mma_bf16(float* c, const uint32_t* a, const uint32_t* b) {
    asm volatile(
        "mma.sync.aligned.m16n8k16.row.col.f32.bf16.bf16.f32 "
        "{%0,%1,%2,%3}, {%4,%5,%6,%7}, {%8,%9}, {%0,%1,%2,%3};"
        : "+f"(c[0]), "+f"(c[1]), "+f"(c[2]), "+f"(c[3])
        : "r"(a[0]), "r"(a[1]), "r"(a[2]), "r"(a[3]), "r"(b[0]), "r"(b[1]));
}
__device__ __forceinline__ void ldsm_x4(uint32_t* r, uint32_t addr) {
    asm volatile("ldmatrix.sync.aligned.m8n8.x4.shared.b16 {%0,%1,%2,%3}, [%4];"
        : "=r"(r[0]), "=r"(r[1]), "=r"(r[2]), "=r"(r[3]) : "r"(addr));
}
__device__ __forceinline__ void ldsm_x4_t(uint32_t* r, uint32_t addr) {
    asm volatile("ldmatrix.sync.aligned.m8n8.x4.trans.shared.b16 {%0,%1,%2,%3}, [%4];"
        : "=r"(r[0]), "=r"(r[1]), "=r"(r[2]), "=r"(r[3]) : "r"(addr));
}
__device__ __forceinline__ uint32_t smem_u32(const void* p) {
    return (uint32_t)__cvta_generic_to_shared(p);
}
__device__ __forceinline__ void cp_async16(uint32_t saddr, const void* gaddr) {
    asm volatile("cp.async.cg.shared.global [%0], [%1], 16;" :: "r"(saddr), "l"(gaddr));
}
#define CP_COMMIT()  asm volatile("cp.async.commit_group;" ::: "memory")
#define CP_WAIT(n)   asm volatile("cp.async.wait_group %0;" :: "n"(n) : "memory")

// pack two f32 -> bf16x2 (lo = first arg in low half)
__device__ __forceinline__ uint32_t packbf(float lo, float hi) {
    uint32_t r;
    asm("cvt.rn.bf16x2.f32 %0, %1, %2;" : "=r"(r) : "f"(hi), "f"(lo));
    return r;
}

// ---------------------------------------------------------------------------
// hi/lo split helpers: x = hi + lo (bf16 each)
// ---------------------------------------------------------------------------
__device__ __forceinline__ void hilo(float x, unsigned short& h, unsigned short& l) {
    __nv_bfloat16 hb = __float2bfloat16_rn(x);
    float r = x - __bfloat162float(hb);
    __nv_bfloat16 lb = __float2bfloat16_rn(r);
    h = __bfloat16_as_ushort(hb);
    l = __bfloat16_as_ushort(lb);
}

// ---------------------------------------------------------------------------
// LayerNorm fused with hi/lo/hi output: one block per row of 1024
// ---------------------------------------------------------------------------
__global__ __launch_bounds__(256) void ln_hilo_kernel(
    const float* __restrict__ x, const float* __restrict__ g,
    const float* __restrict__ b, __nv_bfloat16* __restrict__ y)
{
    __shared__ float red[16];
    const int row = blockIdx.x;
    const int tid = threadIdx.x;
    const float* xr = x + (size_t)row * CC;

    float4 xv = *(const float4*)&xr[tid * 4];
    float s  = xv.x + xv.y + xv.z + xv.w;
    float s2 = xv.x*xv.x + xv.y*xv.y + xv.z*xv.z + xv.w*xv.w;
    #pragma unroll
    for (int o = 16; o > 0; o >>= 1) {
        s  += __shfl_xor_sync(0xffffffffu, s,  o);
        s2 += __shfl_xor_sync(0xffffffffu, s2, o);
    }
    const int warp = tid >> 5;
    if ((tid & 31) == 0) { red[warp] = s; red[warp + 8] = s2; }
    __syncthreads();
    if (tid < 32) {
        float a  = (tid < 8) ? red[tid]     : 0.f;
        float a2 = (tid < 8) ? red[tid + 8] : 0.f;
        #pragma unroll
        for (int o = 4; o > 0; o >>= 1) {
            a  += __shfl_xor_sync(0xffffffffu, a,  o);
            a2 += __shfl_xor_sync(0xffffffffu, a2, o);
        }
        if (tid == 0) { red[0] = a; red[1] = a2; }
    }
    __syncthreads();

    const float mean = red[0] * (1.f / CC);
    const float var  = red[1] * (1.f / CC) - mean * mean;
    const float inv  = rsqrtf(var + 1e-5f);

    float4 gv = *(const float4*)&g[tid * 4];
    float4 bv = *(const float4*)&b[tid * 4];
    float yv[4];
    yv[0] = (xv.x - mean) * inv * gv.x + bv.x;
    yv[1] = (xv.y - mean) * inv * gv.y + bv.y;
    yv[2] = (xv.z - mean) * inv * gv.z + bv.z;
    yv[3] = (xv.w - mean) * inv * gv.w + bv.w;

    ushort4 h4, l4;
    hilo(yv[0], h4.x, l4.x); hilo(yv[1], h4.y, l4.y);
    hilo(yv[2], h4.z, l4.z); hilo(yv[3], h4.w, l4.w);

    __nv_bfloat16* yr = y + (size_t)row * (3 * CC);
    *(ushort4*)&yr[tid * 4]           = h4;
    *(ushort4*)&yr[CC + tid * 4]      = l4;
    *(ushort4*)&yr[2 * CC + tid * 4]  = h4;
}

// ---------------------------------------------------------------------------
// Weight convert + transpose: W[K,N] fp32 -> Bt3[N, 3K] bf16, row n = [hi|hi|lo]
// ---------------------------------------------------------------------------
__global__ __launch_bounds__(256) void conv_b_kernel(
    const float* __restrict__ W, __nv_bfloat16* __restrict__ Y, int K, int N)
{
    __shared__ float t[32][33];
    const int nb = blockIdx.x * 32, kb = blockIdx.y * 32;
    const int tx = threadIdx.x & 31, ty = threadIdx.x >> 5;
    #pragma unroll
    for (int j = 0; j < 32; j += 8)
        t[ty + j][tx] = W[(size_t)(kb + ty + j) * N + nb + tx];
    __syncthreads();
    #pragma unroll
    for (int j = 0; j < 32; j += 8) {
        const int n = nb + ty + j, k = kb + tx;
        unsigned short h, l;
        hilo(t[tx][ty + j], h, l);
        __nv_bfloat16* yr = Y + (size_t)n * (3 * K);
        yr[k]         = __ushort_as_bfloat16(h);
        yr[K + k]     = __ushort_as_bfloat16(h);
        yr[2 * K + k] = __ushort_as_bfloat16(l);
    }
}

// ---------------------------------------------------------------------------
// mma.sync bf16 GEMM with 3-stage cp.async pipeline.
// C[M,N] = epi( A[M,Kp] @ Bt[N,Kp]^T ),  128x128 block, BK=32, 8 warps.
// out_mode: 0 = fp32 (+resid), 1 = bf16 hi/lo/hi [M,3N], 2 = plain bf16 [M,N]
// dynamic smem: A stages at s*5120 halves, B stages at 15360 + s*5120.
// ---------------------------------------------------------------------------
#define LDS_STRIDE 40
#define STG_H      (128 * LDS_STRIDE)          // 5120 halves per matrix-stage
#define GSMEM      (6 * STG_H * 2)             // 61440 bytes

__global__ __launch_bounds__(256, 2) void mma_gemm(
    const __nv_bfloat16* __restrict__ A, const __nv_bfloat16* __restrict__ Bt,
    const float* __restrict__ bias, const float* __restrict__ resid,
    void* __restrict__ Cout, int M, int N, int Kp, int do_gelu, int out_mode)
{
    extern __shared__ __nv_bfloat16 dsm[];

    const int tid  = threadIdx.x;
    const int wid  = tid >> 5;
    const int lane = tid & 31;
    const int row0 = blockIdx.y * 128;
    const int col0 = blockIdx.x * 128;
    const int wm   = (wid & 1) * 64;
    const int wn   = (wid >> 1) * 32;
    const int g    = lane >> 2;
    const int tig  = lane & 3;

    // per-thread load coords (2 chunks of 16B each for A and B)
    const int l_r0 = tid >> 1;                 // rows 0..127 (it=0), +... see below
    const int NT = Kp >> 5;

    float acc[4][4][4];
    #pragma unroll
    for (int mi = 0; mi < 4; mi++)
        #pragma unroll
        for (int ni = 0; ni < 4; ni++)
            #pragma unroll
            for (int c = 0; c < 4; c++) acc[mi][ni][c] = 0.f;

    const int a_r = lane & 15;
    const int a_c = (lane >> 4) * 8;
    const int b_r = (lane & 7) + ((lane >> 4) & 1) * 8;
    const int b_c = ((lane >> 3) & 1) * 8;

    // ---- stage loader: 4 cp.async per thread ----
    auto load_stage = [&](int kt, int s) {
        const __nv_bfloat16* Ag = A  + (size_t)row0 * Kp + kt * 32;
        const __nv_bfloat16* Bg = Bt + (size_t)col0 * Kp + kt * 32;
        __nv_bfloat16* as = dsm + s * STG_H;
        __nv_bfloat16* bs = dsm + 3 * STG_H + s * STG_H;
        #pragma unroll
        for (int it = 0; it < 2; it++) {
            int idx = tid + it * 256;
            int r = idx >> 2, c = (idx & 3) * 8;
            cp_async16(smem_u32(as + r * LDS_STRIDE + c), Ag + (size_t)r * Kp + c);
            cp_async16(smem_u32(bs + r * LDS_STRIDE + c), Bg + (size_t)r * Kp + c);
        }
    };

    load_stage(0, 0); CP_COMMIT();
    load_stage(1, 1); CP_COMMIT();

    int s = 0;
    for (int kt = 0; kt < NT; kt++) {
        CP_WAIT(1);
        __syncthreads();
        // prefetch kt+2 into the buffer freed at kt-1
        if (kt + 2 < NT) load_stage(kt + 2, (s + 2) % 3);
        CP_COMMIT();

        const __nv_bfloat16* as = dsm + s * STG_H;
        const __nv_bfloat16* bs = dsm + 3 * STG_H + s * STG_H;
        #pragma unroll
        for (int ks = 0; ks < 2; ks++) {
            uint32_t a[4][4], b[4][2];
            #pragma unroll
            for (int mi = 0; mi < 4; mi++)
                ldsm_x4(a[mi], smem_u32(as + (wm + mi * 16 + a_r) * LDS_STRIDE + ks * 16 + a_c));
            #pragma unroll
            for (int np = 0; np < 2; np++) {
                uint32_t r[4];
                ldsm_x4(r, smem_u32(bs + (wn + np * 16 + b_r) * LDS_STRIDE + ks * 16 + b_c));
                b[np * 2][0]     = r[0]; b[np * 2][1]     = r[1];
                b[np * 2 + 1][0] = r[2]; b[np * 2 + 1][1] = r[3];
            }
            #pragma unroll
            for (int mi = 0; mi < 4; mi++)
                #pragma unroll
                for (int ni = 0; ni < 4; ni++)
                    mma_bf16(acc[mi][ni], a[mi], b[ni]);
        }
        s = (s + 1) % 3;
    }

    #pragma unroll
    for (int mi = 0; mi < 4; mi++) {
        #pragma unroll
        for (int ni = 0; ni < 4; ni++) {
            const int bc = col0 + wn + ni * 8 + 2 * tig;
            float bx = 0.f, by = 0.f;
            if (bias) { bx = __ldg(&bias[bc]); by = __ldg(&bias[bc + 1]); }
            #pragma unroll
            for (int half = 0; half < 2; half++) {
                const int br = row0 + wm + mi * 16 + g + half * 8;
                float v0 = acc[mi][ni][half * 2 + 0] + bx;
                float v1 = acc[mi][ni][half * 2 + 1] + by;
                if (do_gelu) {
                    v0 = 0.5f * v0 * (1.f + erff(v0 * 0.70710678118654752f));
                    v1 = 0.5f * v1 * (1.f + erff(v1 * 0.70710678118654752f));
                }
                if (out_mode == 1) {
                    __nv_bfloat16* yr = (__nv_bfloat16*)Cout + (size_t)br * (3 * N) + bc;
                    unsigned short h0, l0, h1, l1;
                    hilo(v0, h0, l0); hilo(v1, h1, l1);
                    ushort2 hh = make_ushort2(h0, h1), ll = make_ushort2(l0, l1);
                    *(ushort2*)&yr[0]     = hh;
                    *(ushort2*)&yr[N]     = ll;
                    *(ushort2*)&yr[2 * N] = hh;
                } else if (out_mode == 2) {
                    __nv_bfloat16* yr = (__nv_bfloat16*)Cout + (size_t)br * N + bc;
                    ushort2 hh = make_ushort2(
                        __bfloat16_as_ushort(__float2bfloat16_rn(v0)),
                        __bfloat16_as_ushort(__float2bfloat16_rn(v1)));
                    *(ushort2*)yr = hh;
                } else {
                    float* cr = (float*)Cout + (size_t)br * N + bc;
                    if (resid) {
                        float2 rv = *(const float2*)&resid[(size_t)br * N + bc];
                        v0 += rv.x; v1 += rv.y;
                    }
                    *(float2*)cr = make_float2(v0, v1);
                }
            }
        }
    }
}

// ---------------------------------------------------------------------------
// Tensor-core flash attention (bf16 mma.sync, fp32 softmax/accum).
// CTA: 128 queries, 8 warps x 16 rows. Key blocks of 128.
// Output written DIRECTLY as hi/lo/hi bf16 rows into a3 [MROWS, 3*CC].
// ---------------------------------------------------------------------------
#define AST 72

__global__ __launch_bounds__(256) void attn_mma(
    const __nv_bfloat16* __restrict__ qkv, __nv_bfloat16* __restrict__ a3)
{
    __shared__ __nv_bfloat16 Ks[128][AST];
    __shared__ __nv_bfloat16 Vs[128][AST];

    const int tid  = threadIdx.x;
    const int wid  = tid >> 5;
    const int lane = tid & 31;
    const int b    = blockIdx.y >> 4;
    const int h    = blockIdx.y & 15;
    const int q0   = blockIdx.x * 128;
    const __nv_bfloat16* base = qkv + (size_t)b * NN * (3 * CC);
    const int qc = h * DD;

    const int g = lane >> 2;
    const int t = lane & 3;
    const int a_r  = lane & 15;
    const int a_c  = (lane >> 4) * 8;
    const int kb_r = (lane & 7) + ((lane >> 4) & 1) * 8;
    const int kb_c = ((lane >> 3) & 1) * 8;
    const int vb_r = (lane & 7) + ((lane >> 3) & 1) * 8;
    const int vb_c = ((lane >> 4) & 1) * 8;

    #pragma unroll
    for (int it = 0; it < 4; it++) {
        int idx = tid + it * 256;
        int r = idx >> 3, c8 = (idx & 7) * 8;
        *(uint4*)&Ks[r][c8] = *(const uint4*)&base[(size_t)(q0 + r) * (3 * CC) + qc + c8];
    }
    __syncthreads();
    uint32_t qf[4][4];
    #pragma unroll
    for (int ks = 0; ks < 4; ks++)
        ldsm_x4(qf[ks], smem_u32(&Ks[wid * 16 + a_r][ks * 16 + a_c]));

    float m0 = -1e30f, m1 = -1e30f, l0 = 0.f, l1 = 0.f;
    float oa[8][4];
    #pragma unroll
    for (int nd = 0; nd < 8; nd++)
        #pragma unroll
        for (int c = 0; c < 4; c++) oa[nd][c] = 0.f;

    for (int k0 = 0; k0 < NN; k0 += 128) {
        __syncthreads();
        #pragma unroll
        for (int it = 0; it < 4; it++) {
            int idx = tid + it * 256;
            int r = idx >> 3, c8 = (idx & 7) * 8;
            const size_t gro = (size_t)(k0 + r) * (3 * CC) + qc + c8;
            *(uint4*)&Ks[r][c8] = *(const uint4*)&base[gro + CC];
            *(uint4*)&Vs[r][c8] = *(const uint4*)&base[gro + 2 * CC];
        }
        __syncthreads();

        float s[16][4];
        #pragma unroll
        for (int nt = 0; nt < 16; nt++)
            #pragma unroll
            for (int c = 0; c < 4; c++) s[nt][c] = 0.f;

        #pragma unroll
        for (int ks = 0; ks < 4; ks++) {
            #pragma unroll
            for (int ntp = 0; ntp < 8; ntp++) {
                uint32_t kr[4];
                ldsm_x4(kr, smem_u32(&Ks[ntp * 16 + kb_r][ks * 16 + kb_c]));
                mma_bf16(s[2 * ntp],     qf[ks], kr);
                mma_bf16(s[2 * ntp + 1], qf[ks], kr + 2);
            }
        }

        float tm0 = -1e30f, tm1 = -1e30f;
        #pragma unroll
        for (int nt = 0; nt < 16; nt++) {
            s[nt][0] *= 0.125f; s[nt][1] *= 0.125f;
            s[nt][2] *= 0.125f; s[nt][3] *= 0.125f;
            tm0 = fmaxf(tm0, fmaxf(s[nt][0], s[nt][1]));
            tm1 = fmaxf(tm1, fmaxf(s[nt][2], s[nt][3]));
        }
        tm0 = fmaxf(tm0, __shfl_xor_sync(0xffffffffu, tm0, 1));
        tm0 = fmaxf(tm0, __shfl_xor_sync(0xffffffffu, tm0, 2));
        tm1 = fmaxf(tm1, __shfl_xor_sync(0xffffffffu, tm1, 1));
        tm1 = fmaxf(tm1, __shfl_xor_sync(0xffffffffu, tm1, 2));
        const float m0n = fmaxf(m0, tm0);
        const float m1n = fmaxf(m1, tm1);
        const float al0 = __expf(m0 - m0n);
        const float al1 = __expf(m1 - m1n);

        float r0 = 0.f, r1 = 0.f;
        #pragma unroll
        for (int nt = 0; nt < 16; nt++) {
            s[nt][0] = __expf(s[nt][0] - m0n); r0 += s[nt][0];
            s[nt][1] = __expf(s[nt][1] - m0n); r0 += s[nt][1];
            s[nt][2] = __expf(s[nt][2] - m1n); r1 += s[nt][2];
            s[nt][3] = __expf(s[nt][3] - m1n); r1 += s[nt][3];
        }
        r0 += __shfl_xor_sync(0xffffffffu, r0, 1);
        r0 += __shfl_xor_sync(0xffffffffu, r0, 2);
        r1 += __shfl_xor_sync(0xffffffffu, r1, 1);
        r1 += __shfl_xor_sync(0xffffffffu, r1, 2);
        l0 = l0 * al0 + r0;
        l1 = l1 * al1 + r1;
        m0 = m0n; m1 = m1n;
        #pragma unroll
        for (int nd = 0; nd < 8; nd++) {
            oa[nd][0] *= al0; oa[nd][1] *= al0;
            oa[nd][2] *= al1; oa[nd][3] *= al1;
        }

        uint32_t pf[8][4];
        #pragma unroll
        for (int kt = 0; kt < 8; kt++) {
            pf[kt][0] = packbf(s[2 * kt][0],     s[2 * kt][1]);
            pf[kt][1] = packbf(s[2 * kt][2],     s[2 * kt][3]);
            pf[kt][2] = packbf(s[2 * kt + 1][0], s[2 * kt + 1][1]);
            pf[kt][3] = packbf(s[2 * kt + 1][2], s[2 * kt + 1][3]);
        }

        #pragma unroll
        for (int kt = 0; kt < 8; kt++) {
            #pragma unroll
            for (int ndp = 0; ndp < 4; ndp++) {
                uint32_t vr[4];
                ldsm_x4_t(vr, smem_u32(&Vs[kt * 16 + vb_r][ndp * 16 + vb_c]));
                mma_bf16(oa[2 * ndp],     pf[kt], vr);
                mma_bf16(oa[2 * ndp + 1], pf[kt], vr + 2);
            }
        }
    }

    const float inv0 = 1.f / l0;
    const float inv1 = 1.f / l1;
    const int r0w = b * NN + q0 + wid * 16 + g;
    #pragma unroll
    for (int nd = 0; nd < 8; nd++) {
        const int col = qc + nd * 8 + 2 * t;
        #pragma unroll
        for (int half = 0; half < 2; half++) {
            float v0 = oa[nd][half * 2 + 0] * (half ? inv1 : inv0);
            float v1 = oa[nd][half * 2 + 1] * (half ? inv1 : inv0);
            unsigned short h0, lo0, h1, lo1;
            hilo(v0, h0, lo0); hilo(v1, h1, lo1);
            __nv_bfloat16* yr = a3 + (size_t)(r0w + half * 8) * (3 * CC) + col;
            *(ushort2*)&yr[0]      = make_ushort2(h0, h1);
            *(ushort2*)&yr[CC]     = make_ushort2(lo0, lo1);
            *(ushort2*)&yr[2 * CC] = make_ushort2(h0, h1);
        }
    }
}

// ---------------------------------------------------------------------------
// Launch
// ---------------------------------------------------------------------------
extern "C" void kernel_launch(void* const* d_in, const int* in_sizes, int n_in,
                              void* d_out, int out_size)
{
    const float* x     = (const float*)d_in[0];
    const float* ln1_g = (const float*)d_in[1];
    const float* ln1_b = (const float*)d_in[2];
    const float* w_qkv = (const float*)d_in[3];
    const float* w_prj = (const float*)d_in[4];
    const float* b_prj = (const float*)d_in[5];
    const float* ln2_g = (const float*)d_in[6];
    const float* ln2_b = (const float*)d_in[7];
    const float* w_fc1 = (const float*)d_in[8];
    const float* b_fc1 = (const float*)d_in[9];
    const float* w_fc2 = (const float*)d_in[10];
    const float* b_fc2 = (const float*)d_in[11];
    float* out = (float*)d_out;

    void *p_qkvh, *p_x2, *p_a3, *p_hh3, *p_b3;
    cudaGetSymbolAddress(&p_qkvh, g_qkvh);
    cudaGetSymbolAddress(&p_x2,  g_x2);
    cudaGetSymbolAddress(&p_a3,  g_a3);
    cudaGetSymbolAddress(&p_hh3, g_hh3);
    cudaGetSymbolAddress(&p_b3,  g_b3);
    __nv_bfloat16* qkvh = (__nv_bfloat16*)p_qkvh;
    float* x2  = (float*)p_x2;
    __nv_bfloat16* a3  = (__nv_bfloat16*)p_a3;
    __nv_bfloat16* hh3 = (__nv_bfloat16*)p_hh3;
    __nv_bfloat16* b3  = (__nv_bfloat16*)p_b3;

    static int smem_set = 0;
    if (!smem_set) {
        cudaFuncSetAttribute(mma_gemm, cudaFuncAttributeMaxDynamicSharedMemorySize, GSMEM);
        smem_set = 1;
    }

    // 1. LN1 -> a3 (hi/lo/hi)
    ln_hilo_kernel<<<MROWS, 256>>>(x, ln1_g, ln1_b, a3);
    // 2. w_qkv -> b3 (transposed hi/hi/lo)
    conv_b_kernel<<<dim3(3 * CC / 32, CC / 32), 256>>>(w_qkv, b3, CC, 3 * CC);
    // 3. qkvh = a3 @ b3^T   [4096 x 3072], bf16 out
    mma_gemm<<<dim3(3 * CC / 128, MROWS / 128), 256, GSMEM>>>(
        a3, b3, nullptr, nullptr, qkvh, MROWS, 3 * CC, 3 * CC, 0, 2);
    // 4. attention (tensor core) -> a3 hi/lo/hi directly
    attn_mma<<<dim3(NN / 128, BB * HH), 256>>>(qkvh, a3);
    // 5. w_prj -> b3
    conv_b_kernel<<<dim3(CC / 32, CC / 32), 256>>>(w_prj, b3, CC, CC);
    // 6. x2 = x + a3 @ b3^T + b_prj   [4096 x 1024], fp32 out
    mma_gemm<<<dim3(CC / 128, MROWS / 128), 256, GSMEM>>>(
        a3, b3, b_prj, x, x2, MROWS, CC, 3 * CC, 0, 0);
    // 7. LN2 -> a3
    ln_hilo_kernel<<<MROWS, 256>>>(x2, ln2_g, ln2_b, a3);
    // 8. w_fc1 -> b3
    conv_b_kernel<<<dim3(HID / 32, CC / 32), 256>>>(w_fc1, b3, CC, HID);
    // 9. hh3 = hilo(gelu(a3 @ b3^T + b_fc1))  [4096 x 4096] -> bf16 [4096 x 12288]
    mma_gemm<<<dim3(HID / 128, MROWS / 128), 256, GSMEM>>>(
        a3, b3, b_fc1, nullptr, hh3, MROWS, HID, 3 * CC, 1, 1);
    // 10. w_fc2 -> b3
    conv_b_kernel<<<dim3(CC / 32, HID / 32), 256>>>(w_fc2, b3, HID, CC);
    // 11. out = x2 + hh3 @ b3^T + b_fc2   [4096 x 1024], fp32
    mma_gemm<<<dim3(CC / 128, MROWS / 128), 256, GSMEM>>>(
        hh3, b3, b_fc2, x2, out, MROWS, CC, 3 * HID, 0, 0);
}